// round 1
// baseline (speedup 1.0000x reference)
#include <cuda_runtime.h>
#include <cuda_bf16.h>

// ---------------------------------------------------------------------------
// SAGE_SimWeighted: 3-layer GNN with cosine-similarity softmax edge weights.
// N=50000 nodes, E=1.6M edges, DIN=DH=128, DOUT=64.
//
// Pipeline (all on default stream, graph-capturable, no allocs):
//   0) detect edge_index dtype (int64 vs int32) -> g_is64 flag
//   1) k_init      : zero denom / cnt
//   2) k_norm      : inv row norms of x
//   3) k_edge      : per-edge e=exp(sim/TAU - 2), denom[dst]+=e, cnt[dst]++
//   4) k_scan      : exclusive scan of cnt -> CSR offsets (single block)
//   5) k_scatter   : build CSR (src, w = e/(denom+1e-16))
//   6) per layer l : k_gemm  H @ [Wn|Wr]  -> P, R   (bias cn+cr into R)
//                    k_agg   h' = act(BN( sum_e w*P[src] + R ))
// ---------------------------------------------------------------------------

#define NMAX 50000
#define EMAX 1600000
#define DHD  128

__device__ float g_invn [NMAX];
__device__ float g_denom[NMAX];
__device__ float g_e    [EMAX];
__device__ int   g_cnt  [NMAX];
__device__ int   g_off  [NMAX + 1];
__device__ int   g_cur  [NMAX];
__device__ int   g_csrc [EMAX];
__device__ float g_cw   [EMAX];
__device__ float g_P    [(size_t)NMAX * DHD];
__device__ float g_R    [(size_t)NMAX * DHD];
__device__ float g_H    [(size_t)NMAX * DHD];
__device__ int   g_is64;

// ---------------------------------------------------------------- dtype probe
__global__ void k_detect(const void* ei, int e, int n) {
    __shared__ int bad;
    if (threadIdx.x == 0) bad = 0;
    __syncthreads();
    const long long* p = (const long long*)ei;
    int lim = e < 2048 ? e : 2048;
    for (int i = threadIdx.x; i < lim; i += blockDim.x) {
        long long v = p[i];
        if (v < 0 || v >= (long long)n) bad = 1;
    }
    __syncthreads();
    if (threadIdx.x == 0) g_is64 = bad ? 0 : 1;
}

__device__ __forceinline__ int load_idx(const void* ei, long long pos) {
    if (g_is64) return (int)((const long long*)ei)[pos];
    return ((const int*)ei)[pos];
}

// ---------------------------------------------------------------- init
__global__ void k_init(int n) {
    int i = blockIdx.x * blockDim.x + threadIdx.x;
    if (i < n) { g_denom[i] = 0.f; g_cnt[i] = 0; }
}

// ---------------------------------------------------------------- row norms
__global__ void k_norm(const float* __restrict__ x, int n) {
    int w = (blockIdx.x * blockDim.x + threadIdx.x) >> 5;
    int lane = threadIdx.x & 31;
    if (w >= n) return;
    float4 a = ((const float4*)x)[(size_t)w * 32 + lane];
    float s = a.x * a.x + a.y * a.y + a.z * a.z + a.w * a.w;
    #pragma unroll
    for (int o = 16; o; o >>= 1) s += __shfl_xor_sync(0xffffffffu, s, o);
    if (lane == 0) g_invn[w] = 1.f / (sqrtf(s) + 1e-12f);
}

// ---------------------------------------------------------------- edge pass
// softmax is shift-invariant: use constant shift 2.0 (= max possible logit)
// instead of segment_max. exp(l-2) in [e^-4, 1]; rel deviation vs reference
// from the +1e-16 denominator guard is ~1e-13 -> negligible.
__global__ void k_edge(const float* __restrict__ x, const void* __restrict__ ei,
                       int n, int e) {
    int w = (blockIdx.x * blockDim.x + threadIdx.x) >> 5;
    int lane = threadIdx.x & 31;
    if (w >= e) return;
    int s = load_idx(ei, w);
    int d = load_idx(ei, (long long)e + w);
    float4 a = ((const float4*)x)[(size_t)s * 32 + lane];
    float4 b = ((const float4*)x)[(size_t)d * 32 + lane];
    float dp = a.x * b.x + a.y * b.y + a.z * b.z + a.w * b.w;
    #pragma unroll
    for (int o = 16; o; o >>= 1) dp += __shfl_xor_sync(0xffffffffu, dp, o);
    if (lane == 0) {
        float sim = dp * g_invn[s] * g_invn[d];
        float ev  = __expf(sim * 2.0f - 2.0f);   // /TAU(=0.5) then shift by 2
        g_e[w] = ev;
        atomicAdd(&g_denom[d], ev);
        atomicAdd(&g_cnt[d], 1);
    }
}

// ---------------------------------------------------------------- scan (1 blk)
__global__ void k_scan(int n) {
    __shared__ int warp_excl[32];
    __shared__ int s_tot;
    __shared__ int s_carry;
    int t = threadIdx.x, lane = t & 31, wid = t >> 5;
    if (t == 0) s_carry = 0;
    __syncthreads();
    for (int base = 0; base < n; base += 1024) {
        int i = base + t;
        int v = (i < n) ? g_cnt[i] : 0;
        int x = v;
        #pragma unroll
        for (int o = 1; o < 32; o <<= 1) {
            int y = __shfl_up_sync(0xffffffffu, x, o);
            if (lane >= o) x += y;
        }
        if (lane == 31) warp_excl[wid] = x;   // inclusive warp total
        __syncthreads();
        if (wid == 0) {
            int wv = warp_excl[lane];
            int xx = wv;
            #pragma unroll
            for (int o = 1; o < 32; o <<= 1) {
                int y = __shfl_up_sync(0xffffffffu, xx, o);
                if (lane >= o) xx += y;
            }
            if (lane == 31) s_tot = xx;
            warp_excl[lane] = xx - wv;        // exclusive per-warp offset
        }
        __syncthreads();
        int excl = s_carry + warp_excl[wid] + (x - v);
        if (i < n) { g_off[i] = excl; g_cur[i] = excl; }
        __syncthreads();
        if (t == 0) s_carry += s_tot;
        __syncthreads();
    }
    if (t == 0) g_off[n] = s_carry;
}

// ---------------------------------------------------------------- scatter CSR
__global__ void k_scatter(const void* __restrict__ ei, int e) {
    int i = blockIdx.x * blockDim.x + threadIdx.x;
    if (i >= e) return;
    int s = load_idx(ei, i);
    int d = load_idx(ei, (long long)e + i);
    int pos = atomicAdd(&g_cur[d], 1);
    g_csrc[pos] = s;
    g_cw[pos]   = g_e[i] / (g_denom[d] + 1e-16f);
}

// ---------------------------------------------------------------- fused GEMM
// O = A(n x 128) @ [Wn | Wr](128 x 2*dout);  P gets no bias, R gets cn+cr.
// 64x64 tile, BK=16, 256 thr, 4x4 micro-tile.
__global__ void k_gemm(const float* __restrict__ A,
                       const float* __restrict__ Wn, const float* __restrict__ Wr,
                       const float* __restrict__ cn, const float* __restrict__ cr,
                       float* __restrict__ P, float* __restrict__ Rout,
                       int n, int dout) {
    __shared__ float As[16][64];
    __shared__ float Bs[16][64];
    int tid = threadIdx.x;
    int tx = tid & 15, ty = tid >> 4;
    int m0 = blockIdx.x * 64, c0 = blockIdx.y * 64;
    bool isP = (c0 < dout);
    const float* B = isP ? Wn : Wr;
    int cb = isP ? c0 : (c0 - dout);

    float acc[4][4] = {};
    int arow = tid >> 2;          // 0..63
    int akq  = (tid & 3) * 4;     // 0,4,8,12
    int brow = tid >> 4;          // 0..15
    int bcol = (tid & 15) * 4;    // 0..60

    for (int k0 = 0; k0 < 128; k0 += 16) {
        float4 av = make_float4(0.f, 0.f, 0.f, 0.f);
        int gm = m0 + arow;
        if (gm < n) av = *(const float4*)(A + (size_t)gm * 128 + k0 + akq);
        As[akq + 0][arow] = av.x;
        As[akq + 1][arow] = av.y;
        As[akq + 2][arow] = av.z;
        As[akq + 3][arow] = av.w;
        float4 bv = *(const float4*)(B + (size_t)(k0 + brow) * dout + cb + bcol);
        *(float4*)&Bs[brow][bcol] = bv;
        __syncthreads();
        #pragma unroll
        for (int k = 0; k < 16; k++) {
            float4 a = *(float4*)&As[k][ty * 4];
            float4 b = *(float4*)&Bs[k][tx * 4];
            float ar[4] = {a.x, a.y, a.z, a.w};
            float br[4] = {b.x, b.y, b.z, b.w};
            #pragma unroll
            for (int i = 0; i < 4; i++)
                #pragma unroll
                for (int j = 0; j < 4; j++)
                    acc[i][j] += ar[i] * br[j];
        }
        __syncthreads();
    }

    float bias[4];
    #pragma unroll
    for (int j = 0; j < 4; j++) {
        int c = cb + tx * 4 + j;
        bias[j] = isP ? 0.f : (cn[c] + cr[c]);
    }
    float* O = isP ? P : Rout;
    #pragma unroll
    for (int i = 0; i < 4; i++) {
        int gm = m0 + ty * 4 + i;
        if (gm >= n) continue;
        float4 o = make_float4(acc[i][0] + bias[0], acc[i][1] + bias[1],
                               acc[i][2] + bias[2], acc[i][3] + bias[3]);
        *(float4*)(O + (size_t)gm * dout + cb + tx * 4) = o;
    }
}

// ---------------------------------------------------------------- aggregate
// warp per node: acc = sum_e w_e * P[src], then h = act(BN(acc + R[node])).
template <int DO, bool DOBN>
__global__ void k_agg(const float* __restrict__ P, const float* __restrict__ R,
                      const float* __restrict__ gg, const float* __restrict__ bb,
                      const float* __restrict__ mm, const float* __restrict__ vv,
                      float* __restrict__ out, int n) {
    int w = (blockIdx.x * blockDim.x + threadIdx.x) >> 5;
    int lane = threadIdx.x & 31;
    if (w >= n) return;
    constexpr int V = DO / 32;       // 4 or 2 floats per lane
    float acc[V];
    #pragma unroll
    for (int c = 0; c < V; c++) acc[c] = 0.f;

    int s = g_off[w], e = g_off[w + 1];
    for (int base = s; base < e; base += 32) {
        int idx = base + lane;
        int sj = 0; float wj = 0.f;
        if (idx < e) { sj = g_csrc[idx]; wj = g_cw[idx]; }
        int cnt = min(32, e - base);
        for (int j = 0; j < cnt; j++) {
            int   s2 = __shfl_sync(0xffffffffu, sj, j);
            float w2 = __shfl_sync(0xffffffffu, wj, j);
            if constexpr (V == 4) {
                float4 p = ((const float4*)(P + (size_t)s2 * DO))[lane];
                acc[0] += w2 * p.x; acc[1] += w2 * p.y;
                acc[2] += w2 * p.z; acc[3] += w2 * p.w;
            } else {
                float2 p = ((const float2*)(P + (size_t)s2 * DO))[lane];
                acc[0] += w2 * p.x; acc[1] += w2 * p.y;
            }
        }
    }

    float r[V];
    if constexpr (V == 4) {
        float4 rv = ((const float4*)(R + (size_t)w * DO))[lane];
        r[0] = rv.x; r[1] = rv.y; r[2] = rv.z; r[3] = rv.w;
    } else {
        float2 rv = ((const float2*)(R + (size_t)w * DO))[lane];
        r[0] = rv.x; r[1] = rv.y;
    }

    float h[V];
    #pragma unroll
    for (int c = 0; c < V; c++) {
        int d = lane * V + c;
        float hv = acc[c] + r[c];
        if (DOBN) {
            float sc = gg[d] * rsqrtf(vv[d] + 1e-5f);
            hv = (hv - mm[d]) * sc + bb[d];
            hv = fmaxf(hv, 0.f);
        }
        h[c] = hv;
    }
    if constexpr (V == 4) {
        ((float4*)(out + (size_t)w * DO))[lane] = make_float4(h[0], h[1], h[2], h[3]);
    } else {
        ((float2*)(out + (size_t)w * DO))[lane] = make_float2(h[0], h[1]);
    }
}

// ---------------------------------------------------------------- launch
extern "C" void kernel_launch(void* const* d_in, const int* in_sizes, int n_in,
                              void* d_out, int out_size) {
    const float* x   = (const float*)d_in[0];
    const void*  ei  = d_in[1];
    const float* Wn0 = (const float*)d_in[2];
    const float* cn0 = (const float*)d_in[3];
    const float* Wr0 = (const float*)d_in[4];
    const float* cr0 = (const float*)d_in[5];
    const float* Wn1 = (const float*)d_in[6];
    const float* cn1 = (const float*)d_in[7];
    const float* Wr1 = (const float*)d_in[8];
    const float* cr1 = (const float*)d_in[9];
    const float* Wn2 = (const float*)d_in[10];
    const float* cn2 = (const float*)d_in[11];
    const float* Wr2 = (const float*)d_in[12];
    const float* cr2 = (const float*)d_in[13];
    const float* g0  = (const float*)d_in[14];
    const float* b0  = (const float*)d_in[15];
    const float* m0  = (const float*)d_in[16];
    const float* v0  = (const float*)d_in[17];
    const float* g1  = (const float*)d_in[18];
    const float* b1  = (const float*)d_in[19];
    const float* m1  = (const float*)d_in[20];
    const float* v1  = (const float*)d_in[21];

    int n = in_sizes[0] / 128;
    int e = in_sizes[1] / 2;
    float* out = (float*)d_out;

    float *P, *R, *H;
    cudaGetSymbolAddress((void**)&P, g_P);
    cudaGetSymbolAddress((void**)&R, g_R);
    cudaGetSymbolAddress((void**)&H, g_H);

    k_detect<<<1, 256>>>(ei, e, n);
    k_init<<<(n + 255) / 256, 256>>>(n);
    k_norm<<<(n + 7) / 8, 256>>>(x, n);
    k_edge<<<(e + 7) / 8, 256>>>(x, ei, n, e);
    k_scan<<<1, 1024>>>(n);
    k_scatter<<<(e + 255) / 256, 256>>>(ei, e);

    dim3 gblk(256);
    // layer 0
    k_gemm<<<dim3((n + 63) / 64, 4), gblk>>>(x, Wn0, Wr0, cn0, cr0, P, R, n, 128);
    k_agg<128, true><<<(n + 7) / 8, 256>>>(P, R, g0, b0, m0, v0, H, n);
    // layer 1
    k_gemm<<<dim3((n + 63) / 64, 4), gblk>>>(H, Wn1, Wr1, cn1, cr1, P, R, n, 128);
    k_agg<128, true><<<(n + 7) / 8, 256>>>(P, R, g1, b1, m1, v1, H, n);
    // layer 2 (no BN/relu)
    k_gemm<<<dim3((n + 63) / 64, 2), gblk>>>(H, Wn2, Wr2, cn2, cr2, P, R, n, 64);
    k_agg<64, false><<<(n + 7) / 8, 256>>>(P, R, g0, b0, m0, v0, out, n);
}

// round 2
// speedup vs baseline: 1.3443x; 1.3443x over previous
#include <cuda_runtime.h>
#include <cuda_bf16.h>

// ---------------------------------------------------------------------------
// SAGE_SimWeighted: 3-layer GNN, cosine-sim softmax edge weights.
// N=50000, E=1.6M, DIN=DH=128, DOUT=64.
//
//   k_detect -> k_init -> k_norm -> k_edge (8 lanes/edge, raw e + atomics)
//   -> k_scan (CSR offsets) -> k_scatter (packed int2 {src, raw_e})
//   -> per layer: k_gemm (128x128 tile, FFMA2 f32x2, PR fused output)
//                 k_agg  (warp/node, broadcast int2, /denom once per node)
// ---------------------------------------------------------------------------

#define NMAX 50000
#define EMAX 1600000

__device__ float g_invn [NMAX];
__device__ float g_denom[NMAX];
__device__ float g_e    [EMAX];
__device__ int   g_cnt  [NMAX];
__device__ int   g_off  [NMAX + 1];
__device__ int   g_cur  [NMAX];
__device__ int2  g_csw  [EMAX];                    // {src, raw_e bits}
__device__ float g_PR   [(size_t)NMAX * 256];      // [P | R] fused
__device__ float g_H    [(size_t)NMAX * 128];
__device__ int   g_is64;

// ---------------------------------------------------------------- f32x2 utils
__device__ __forceinline__ unsigned long long pack2(float lo, float hi) {
    unsigned long long r;
    asm("mov.b64 %0, {%1, %2};" : "=l"(r) : "f"(lo), "f"(hi));
    return r;
}
__device__ __forceinline__ unsigned long long fma2(unsigned long long a,
                                                   unsigned long long b,
                                                   unsigned long long c) {
    unsigned long long d;
    asm("fma.rn.f32x2 %0, %1, %2, %3;" : "=l"(d) : "l"(a), "l"(b), "l"(c));
    return d;
}
__device__ __forceinline__ void unpack2(unsigned long long v, float& lo, float& hi) {
    asm("mov.b64 {%0, %1}, %2;" : "=f"(lo), "=f"(hi) : "l"(v));
}

// ---------------------------------------------------------------- dtype probe
__global__ void k_detect(const void* ei, int e, int n) {
    __shared__ int bad;
    if (threadIdx.x == 0) bad = 0;
    __syncthreads();
    const long long* p = (const long long*)ei;
    int lim = e < 2048 ? e : 2048;
    for (int i = threadIdx.x; i < lim; i += blockDim.x) {
        long long v = p[i];
        if (v < 0 || v >= (long long)n) bad = 1;
    }
    __syncthreads();
    if (threadIdx.x == 0) g_is64 = bad ? 0 : 1;
}

__device__ __forceinline__ int load_idx(const void* ei, long long pos) {
    if (g_is64) return (int)((const long long*)ei)[pos];
    return ((const int*)ei)[pos];
}

// ---------------------------------------------------------------- init
__global__ void k_init(int n) {
    int i = blockIdx.x * blockDim.x + threadIdx.x;
    if (i < n) { g_denom[i] = 0.f; g_cnt[i] = 0; }
}

// ---------------------------------------------------------------- row norms
__global__ void k_norm(const float* __restrict__ x, int n) {
    int w = (blockIdx.x * blockDim.x + threadIdx.x) >> 5;
    int lane = threadIdx.x & 31;
    if (w >= n) return;
    float4 a = ((const float4*)x)[(size_t)w * 32 + lane];
    float s = a.x * a.x + a.y * a.y + a.z * a.z + a.w * a.w;
    #pragma unroll
    for (int o = 16; o; o >>= 1) s += __shfl_xor_sync(0xffffffffu, s, o);
    if (lane == 0) g_invn[w] = 1.f / (sqrtf(s) + 1e-12f);
}

// ---------------------------------------------------------------- edge pass
// 8 lanes per edge; lane t loads float4 at t*16B + j*128B (one 128B line per
// 8-lane group per j). softmax shift = constant 2.0 (max possible logit).
__global__ void k_edge(const float* __restrict__ x, const void* __restrict__ ei,
                       int n, int e) {
    int lane = threadIdx.x & 31;
    int t = lane & 7;
    long long eIdx = (long long)blockIdx.x * (blockDim.x >> 3) + (threadIdx.x >> 3);
    if (eIdx >= e) return;
    int s = load_idx(ei, eIdx);              // broadcast within 8-lane group
    int d = load_idx(ei, (long long)e + eIdx);
    const float4* ap = (const float4*)(x + (size_t)s * 128);
    const float4* bp = (const float4*)(x + (size_t)d * 128);
    float dp = 0.f;
    #pragma unroll
    for (int j = 0; j < 4; j++) {
        float4 a = ap[t + j * 8];
        float4 b = bp[t + j * 8];
        dp += a.x * b.x + a.y * b.y + a.z * b.z + a.w * b.w;
    }
    #pragma unroll
    for (int o = 4; o; o >>= 1) dp += __shfl_xor_sync(0xffffffffu, dp, o);
    if (t == 0) {
        float sim = dp * g_invn[s] * g_invn[d];
        float ev  = __expf(sim * 2.0f - 2.0f);   // /TAU(0.5), shift by 2
        g_e[eIdx] = ev;
        atomicAdd(&g_denom[d], ev);
        atomicAdd(&g_cnt[d], 1);
    }
}

// ---------------------------------------------------------------- scan (1 blk)
__global__ void k_scan(int n) {
    __shared__ int warp_excl[32];
    __shared__ int s_tot;
    __shared__ int s_carry;
    int t = threadIdx.x, lane = t & 31, wid = t >> 5;
    if (t == 0) s_carry = 0;
    __syncthreads();
    for (int base = 0; base < n; base += 1024) {
        int i = base + t;
        int v = (i < n) ? g_cnt[i] : 0;
        int x = v;
        #pragma unroll
        for (int o = 1; o < 32; o <<= 1) {
            int y = __shfl_up_sync(0xffffffffu, x, o);
            if (lane >= o) x += y;
        }
        if (lane == 31) warp_excl[wid] = x;
        __syncthreads();
        if (wid == 0) {
            int wv = warp_excl[lane];
            int xx = wv;
            #pragma unroll
            for (int o = 1; o < 32; o <<= 1) {
                int y = __shfl_up_sync(0xffffffffu, xx, o);
                if (lane >= o) xx += y;
            }
            if (lane == 31) s_tot = xx;
            warp_excl[lane] = xx - wv;
        }
        __syncthreads();
        int excl = s_carry + warp_excl[wid] + (x - v);
        if (i < n) { g_off[i] = excl; g_cur[i] = excl; }
        __syncthreads();
        if (t == 0) s_carry += s_tot;
        __syncthreads();
    }
    if (t == 0) g_off[n] = s_carry;
}

// ---------------------------------------------------------------- scatter CSR
__global__ void k_scatter(const void* __restrict__ ei, int e) {
    int i = blockIdx.x * blockDim.x + threadIdx.x;
    if (i >= e) return;
    int s = load_idx(ei, i);
    int d = load_idx(ei, (long long)e + i);
    int pos = atomicAdd(&g_cur[d], 1);
    g_csw[pos] = make_int2(s, __float_as_int(g_e[i]));
}

// ---------------------------------------------------------------- fused GEMM
// O[n x 2*dout] = A[n x 128] @ [Wn | Wr]; R half gets bias cn+cr.
// 128x128 block tile, BK=8, 256 threads, 8x8 micro-tile, f32x2 FFMA2.
__global__ void __launch_bounds__(256, 2)
k_gemm(const float* __restrict__ A,
       const float* __restrict__ Wn, const float* __restrict__ Wr,
       const float* __restrict__ cn, const float* __restrict__ cr,
       float* __restrict__ O, int n, int dout) {
    __shared__ float As[8][132];   // padded: conflict-free transposed stores
    __shared__ float Bs[8][128];
    int tid = threadIdx.x;
    int tx = tid & 15, ty = tid >> 4;
    int m0 = blockIdx.x * 128, c0 = blockIdx.y * 128;
    int W = 2 * dout;

    int amm = tid >> 1;            // 0..127
    int akq = (tid & 1) * 4;       // 0 or 4
    int bkk = tid >> 5;            // 0..7
    int bcc = (tid & 31) * 4;      // 0..124

    int cglob = c0 + bcc;
    const float* Bsrc = (cglob < dout) ? Wn : Wr;
    int bcol = (cglob < dout) ? cglob : cglob - dout;

    unsigned long long acc[8][4];
    #pragma unroll
    for (int i = 0; i < 8; i++)
        #pragma unroll
        for (int q = 0; q < 4; q++) acc[i][q] = 0ULL;

    int gm = m0 + amm;
    float4 areg = make_float4(0.f, 0.f, 0.f, 0.f);
    if (gm < n) areg = *(const float4*)(A + (size_t)gm * 128 + akq);
    float4 breg = *(const float4*)(Bsrc + (size_t)bkk * dout + bcol);

    for (int k0 = 0;;) {
        As[akq + 0][amm] = areg.x;
        As[akq + 1][amm] = areg.y;
        As[akq + 2][amm] = areg.z;
        As[akq + 3][amm] = areg.w;
        *(float4*)&Bs[bkk][bcc] = breg;
        __syncthreads();
        int knext = k0 + 8;
        if (knext < 128) {
            if (gm < n) areg = *(const float4*)(A + (size_t)gm * 128 + knext + akq);
            breg = *(const float4*)(Bsrc + (size_t)(knext + bkk) * dout + bcol);
        }
        #pragma unroll
        for (int kk = 0; kk < 8; kk++) {
            float4 a0 = *(float4*)&As[kk][ty * 8];
            float4 a1 = *(float4*)&As[kk][ty * 8 + 4];
            ulonglong2 b0 = *(ulonglong2*)&Bs[kk][tx * 4];
            ulonglong2 b1 = *(ulonglong2*)&Bs[kk][64 + tx * 4];
            float av[8] = {a0.x, a0.y, a0.z, a0.w, a1.x, a1.y, a1.z, a1.w};
            #pragma unroll
            for (int i = 0; i < 8; i++) {
                unsigned long long ap = pack2(av[i], av[i]);
                acc[i][0] = fma2(ap, b0.x, acc[i][0]);
                acc[i][1] = fma2(ap, b0.y, acc[i][1]);
                acc[i][2] = fma2(ap, b1.x, acc[i][2]);
                acc[i][3] = fma2(ap, b1.y, acc[i][3]);
            }
        }
        k0 = knext;
        if (k0 >= 128) break;
        __syncthreads();
    }

    float bias[8];
    #pragma unroll
    for (int j = 0; j < 8; j++) {
        int c = c0 + (j < 4 ? tx * 4 + j : 64 + tx * 4 + (j - 4));
        bias[j] = (c < dout) ? 0.f : (cn[c - dout] + cr[c - dout]);
    }
    #pragma unroll
    for (int i = 0; i < 8; i++) {
        int m = m0 + ty * 8 + i;
        if (m >= n) continue;
        float v[8];
        unpack2(acc[i][0], v[0], v[1]);
        unpack2(acc[i][1], v[2], v[3]);
        unpack2(acc[i][2], v[4], v[5]);
        unpack2(acc[i][3], v[6], v[7]);
        float4 o0 = make_float4(v[0] + bias[0], v[1] + bias[1],
                                v[2] + bias[2], v[3] + bias[3]);
        float4 o1 = make_float4(v[4] + bias[4], v[5] + bias[5],
                                v[6] + bias[6], v[7] + bias[7]);
        *(float4*)(O + (size_t)m * W + c0 + tx * 4) = o0;
        *(float4*)(O + (size_t)m * W + c0 + 64 + tx * 4) = o1;
    }
}

// ---------------------------------------------------------------- aggregate
// warp per node: acc = sum_e rawE_e * P[src]; h = act(BN(acc/denom + R)).
// PR layout: row = [P(0..DO) | R(DO..2DO)].
template <int DO, bool DOBN>
__global__ void k_agg(const float* __restrict__ PR,
                      const float* __restrict__ gg, const float* __restrict__ bb,
                      const float* __restrict__ mm, const float* __restrict__ vv,
                      float* __restrict__ out, int n) {
    int w = (blockIdx.x * blockDim.x + threadIdx.x) >> 5;
    int lane = threadIdx.x & 31;
    if (w >= n) return;
    constexpr int V = DO / 32;
    constexpr int WI = 2 * DO;
    float acc[V];
    #pragma unroll
    for (int c = 0; c < V; c++) acc[c] = 0.f;

    int s = g_off[w], e2 = g_off[w + 1];
    #pragma unroll 2
    for (int idx = s; idx < e2; idx++) {
        int2 v = __ldg(&g_csw[idx]);             // broadcast: 1 wavefront
        float w2 = __int_as_float(v.y);
        const float* prow = PR + (size_t)v.x * WI;
        if constexpr (V == 4) {
            float4 p = ((const float4*)prow)[lane];
            acc[0] += w2 * p.x; acc[1] += w2 * p.y;
            acc[2] += w2 * p.z; acc[3] += w2 * p.w;
        } else {
            float2 p = ((const float2*)prow)[lane];
            acc[0] += w2 * p.x; acc[1] += w2 * p.y;
        }
    }
    float inv = 1.f / (g_denom[w] + 1e-16f);

    float r[V];
    const float* rrow = PR + (size_t)w * WI + DO;
    if constexpr (V == 4) {
        float4 rv = ((const float4*)rrow)[lane];
        r[0] = rv.x; r[1] = rv.y; r[2] = rv.z; r[3] = rv.w;
    } else {
        float2 rv = ((const float2*)rrow)[lane];
        r[0] = rv.x; r[1] = rv.y;
    }

    float h[V];
    #pragma unroll
    for (int c = 0; c < V; c++) {
        int d = lane * V + c;
        float hv = acc[c] * inv + r[c];
        if (DOBN) {
            float sc = gg[d] * rsqrtf(vv[d] + 1e-5f);
            hv = (hv - mm[d]) * sc + bb[d];
            hv = fmaxf(hv, 0.f);
        }
        h[c] = hv;
    }
    if constexpr (V == 4) {
        ((float4*)(out + (size_t)w * DO))[lane] = make_float4(h[0], h[1], h[2], h[3]);
    } else {
        ((float2*)(out + (size_t)w * DO))[lane] = make_float2(h[0], h[1]);
    }
}

// ---------------------------------------------------------------- launch
extern "C" void kernel_launch(void* const* d_in, const int* in_sizes, int n_in,
                              void* d_out, int out_size) {
    const float* x   = (const float*)d_in[0];
    const void*  ei  = d_in[1];
    const float* Wn0 = (const float*)d_in[2];
    const float* cn0 = (const float*)d_in[3];
    const float* Wr0 = (const float*)d_in[4];
    const float* cr0 = (const float*)d_in[5];
    const float* Wn1 = (const float*)d_in[6];
    const float* cn1 = (const float*)d_in[7];
    const float* Wr1 = (const float*)d_in[8];
    const float* cr1 = (const float*)d_in[9];
    const float* Wn2 = (const float*)d_in[10];
    const float* cn2 = (const float*)d_in[11];
    const float* Wr2 = (const float*)d_in[12];
    const float* cr2 = (const float*)d_in[13];
    const float* g0  = (const float*)d_in[14];
    const float* b0  = (const float*)d_in[15];
    const float* m0  = (const float*)d_in[16];
    const float* v0  = (const float*)d_in[17];
    const float* g1  = (const float*)d_in[18];
    const float* b1  = (const float*)d_in[19];
    const float* m1  = (const float*)d_in[20];
    const float* v1  = (const float*)d_in[21];

    int n = in_sizes[0] / 128;
    int e = in_sizes[1] / 2;
    float* out = (float*)d_out;

    float *PR, *H;
    cudaGetSymbolAddress((void**)&PR, g_PR);
    cudaGetSymbolAddress((void**)&H, g_H);

    k_detect<<<1, 256>>>(ei, e, n);
    k_init<<<(n + 255) / 256, 256>>>(n);
    k_norm<<<(n + 7) / 8, 256>>>(x, n);
    k_edge<<<(e + 31) / 32, 256>>>(x, ei, n, e);
    k_scan<<<1, 1024>>>(n);
    k_scatter<<<(e + 255) / 256, 256>>>(ei, e);

    int gx = (n + 127) / 128;
    // layer 0
    k_gemm<<<dim3(gx, 2), 256>>>(x, Wn0, Wr0, cn0, cr0, PR, n, 128);
    k_agg<128, true><<<(n + 7) / 8, 256>>>(PR, g0, b0, m0, v0, H, n);
    // layer 1
    k_gemm<<<dim3(gx, 2), 256>>>(H, Wn1, Wr1, cn1, cr1, PR, n, 128);
    k_agg<128, true><<<(n + 7) / 8, 256>>>(PR, g1, b1, m1, v1, H, n);
    // layer 2 (no BN/relu)
    k_gemm<<<dim3(gx, 1), 256>>>(H, Wn2, Wr2, cn2, cr2, PR, n, 64);
    k_agg<64, false><<<(n + 7) / 8, 256>>>(PR, g0, b0, m0, v0, out, n);
}

// round 3
// speedup vs baseline: 1.4303x; 1.0640x over previous
#include <cuda_runtime.h>
#include <cuda_bf16.h>

// ---------------------------------------------------------------------------
// SAGE_SimWeighted: 3-layer GNN, cosine-sim softmax edge weights.
// N=50000, E=1.6M, DIN=DH=128, DOUT=64.
//
//   null stream: detect -> init -> norm(x->xn) -> cnt -> scan -> place
//                -> edge_csr (warp/node: dst row in regs, src gathered,
//                             denom = warp reduction, w written in CSR order)
//                -> [join gemm0] agg0 -> gemm1 -> agg1 -> gemm2 -> agg2
//   stream 2   : gemm0 (depends only on x) overlapped with the edge chain.
// ---------------------------------------------------------------------------

#define NMAX 50000
#define EMAX 1600000

__device__ float g_xn   [(size_t)NMAX * 128];      // normalized x
__device__ int   g_cnt  [NMAX];
__device__ int   g_off  [NMAX + 1];
__device__ int   g_cur  [NMAX];
__device__ int2  g_csw  [EMAX];                    // {src, w bits}
__device__ float g_PR   [(size_t)NMAX * 256];      // [P | R] fused
__device__ float g_H    [(size_t)NMAX * 128];
__device__ int   g_is64;

// ---------------------------------------------------------------- f32x2 utils
__device__ __forceinline__ unsigned long long pack2(float lo, float hi) {
    unsigned long long r;
    asm("mov.b64 %0, {%1, %2};" : "=l"(r) : "f"(lo), "f"(hi));
    return r;
}
__device__ __forceinline__ unsigned long long fma2(unsigned long long a,
                                                   unsigned long long b,
                                                   unsigned long long c) {
    unsigned long long d;
    asm("fma.rn.f32x2 %0, %1, %2, %3;" : "=l"(d) : "l"(a), "l"(b), "l"(c));
    return d;
}
__device__ __forceinline__ void unpack2(unsigned long long v, float& lo, float& hi) {
    asm("mov.b64 {%0, %1}, %2;" : "=f"(lo), "=f"(hi) : "l"(v));
}

// ---------------------------------------------------------------- dtype probe
__global__ void k_detect(const void* ei, int e, int n) {
    __shared__ int bad;
    if (threadIdx.x == 0) bad = 0;
    __syncthreads();
    const long long* p = (const long long*)ei;
    int lim = e < 2048 ? e : 2048;
    for (int i = threadIdx.x; i < lim; i += blockDim.x) {
        long long v = p[i];
        if (v < 0 || v >= (long long)n) bad = 1;
    }
    __syncthreads();
    if (threadIdx.x == 0) g_is64 = bad ? 0 : 1;
}

__device__ __forceinline__ int load_idx(const void* ei, long long pos) {
    if (g_is64) return (int)((const long long*)ei)[pos];
    return ((const int*)ei)[pos];
}

// ---------------------------------------------------------------- init
__global__ void k_init(int n) {
    int i = blockIdx.x * blockDim.x + threadIdx.x;
    if (i < n) g_cnt[i] = 0;
}

// ---------------------------------------------------------------- normalize x
__global__ void k_norm(const float* __restrict__ x, int n) {
    int w = (blockIdx.x * blockDim.x + threadIdx.x) >> 5;
    int lane = threadIdx.x & 31;
    if (w >= n) return;
    float4 a = ((const float4*)x)[(size_t)w * 32 + lane];
    float s = a.x * a.x + a.y * a.y + a.z * a.z + a.w * a.w;
    #pragma unroll
    for (int o = 16; o; o >>= 1) s += __shfl_xor_sync(0xffffffffu, s, o);
    float inv = 1.f / (sqrtf(s) + 1e-12f);
    float4 o = make_float4(a.x * inv, a.y * inv, a.z * inv, a.w * inv);
    ((float4*)g_xn)[(size_t)w * 32 + lane] = o;
}

// ---------------------------------------------------------------- degree cnt
__global__ void k_cnt(const void* __restrict__ ei, int e) {
    int i = blockIdx.x * blockDim.x + threadIdx.x;
    if (i >= e) return;
    int d = load_idx(ei, (long long)e + i);
    atomicAdd(&g_cnt[d], 1);
}

// ---------------------------------------------------------------- scan (1 blk)
__global__ void k_scan(int n) {
    __shared__ int warp_excl[32];
    __shared__ int s_tot;
    __shared__ int s_carry;
    int t = threadIdx.x, lane = t & 31, wid = t >> 5;
    if (t == 0) s_carry = 0;
    __syncthreads();
    for (int base = 0; base < n; base += 1024) {
        int i = base + t;
        int v = (i < n) ? g_cnt[i] : 0;
        int x = v;
        #pragma unroll
        for (int o = 1; o < 32; o <<= 1) {
            int y = __shfl_up_sync(0xffffffffu, x, o);
            if (lane >= o) x += y;
        }
        if (lane == 31) warp_excl[wid] = x;
        __syncthreads();
        if (wid == 0) {
            int wv = warp_excl[lane];
            int xx = wv;
            #pragma unroll
            for (int o = 1; o < 32; o <<= 1) {
                int y = __shfl_up_sync(0xffffffffu, xx, o);
                if (lane >= o) xx += y;
            }
            if (lane == 31) s_tot = xx;
            warp_excl[lane] = xx - wv;
        }
        __syncthreads();
        int excl = s_carry + warp_excl[wid] + (x - v);
        if (i < n) { g_off[i] = excl; g_cur[i] = excl; }
        __syncthreads();
        if (t == 0) s_carry += s_tot;
        __syncthreads();
    }
    if (t == 0) g_off[n] = s_carry;
}

// ---------------------------------------------------------------- place srcs
__global__ void k_place(const void* __restrict__ ei, int e) {
    int i = blockIdx.x * blockDim.x + threadIdx.x;
    if (i >= e) return;
    int s = load_idx(ei, i);
    int d = load_idx(ei, (long long)e + i);
    int pos = atomicAdd(&g_cur[d], 1);
    ((int*)g_csw)[2 * pos] = s;
}

// ---------------------------------------------------------------- edge weights
// warp per dst node; 4 groups of 8 lanes; group g handles edges g, g+4, ...
// dst row (normalized) lives in registers; src rows gathered (512B/edge).
// softmax shift = constant 2.0 (max possible logit, since |sim| <= 1).
__global__ void k_edge_csr(int n) {
    int w = (blockIdx.x * blockDim.x + threadIdx.x) >> 5;
    int lane = threadIdx.x & 31;
    if (w >= n) return;
    int g = lane >> 3, t = lane & 7;
    unsigned gmask = 0xFFu << (g * 8);
    int s0 = g_off[w], e0 = g_off[w + 1];
    int nE = e0 - s0;
    if (nE == 0) return;

    float4 dreg[4];
    const float4* dp = (const float4*)(g_xn + (size_t)w * 128);
    #pragma unroll
    for (int j = 0; j < 4; j++) dreg[j] = dp[t + j * 8];

    float dsum = 0.f;
    for (int i = g; i < nE; i += 4) {
        int pos = s0 + i;
        int sidx = ((const int*)g_csw)[2 * pos];     // broadcast within group
        const float4* sp = (const float4*)(g_xn + (size_t)sidx * 128);
        float dpacc = 0.f;
        #pragma unroll
        for (int j = 0; j < 4; j++) {
            float4 a = sp[t + j * 8];
            dpacc += a.x * dreg[j].x + a.y * dreg[j].y
                   + a.z * dreg[j].z + a.w * dreg[j].w;
        }
        dpacc += __shfl_xor_sync(gmask, dpacc, 4);
        dpacc += __shfl_xor_sync(gmask, dpacc, 2);
        dpacc += __shfl_xor_sync(gmask, dpacc, 1);
        if (t == 0) {
            float ev = __expf(dpacc * 2.0f - 2.0f);  // /TAU(0.5), shift 2
            ((int*)g_csw)[2 * pos + 1] = __float_as_int(ev);
            dsum += ev;
        }
    }
    if (t != 0) dsum = 0.f;
    __syncwarp();
    dsum += __shfl_xor_sync(0xffffffffu, dsum, 8);
    dsum += __shfl_xor_sync(0xffffffffu, dsum, 16);
    float inv = 1.f / (__shfl_sync(0xffffffffu, dsum, 0) + 1e-16f);
    for (int i = lane; i < nE; i += 32) {
        int q = 2 * (s0 + i) + 1;
        float ev = __int_as_float(((int*)g_csw)[q]);
        ((int*)g_csw)[q] = __float_as_int(ev * inv);
    }
}

// ---------------------------------------------------------------- fused GEMM
// O[n x 2*dout] = A[n x 128] @ [Wn | Wr]; R half gets bias cn+cr.
// 128x128 block tile, BK=8, 256 threads, 8x8 micro-tile, f32x2 FFMA2.
__global__ void __launch_bounds__(256, 2)
k_gemm(const float* __restrict__ A,
       const float* __restrict__ Wn, const float* __restrict__ Wr,
       const float* __restrict__ cn, const float* __restrict__ cr,
       float* __restrict__ O, int n, int dout) {
    __shared__ float As[8][132];
    __shared__ float Bs[8][128];
    int tid = threadIdx.x;
    int tx = tid & 15, ty = tid >> 4;
    int m0 = blockIdx.x * 128, c0 = blockIdx.y * 128;
    int W = 2 * dout;

    int amm = tid >> 1;
    int akq = (tid & 1) * 4;
    int bkk = tid >> 5;
    int bcc = (tid & 31) * 4;

    int cglob = c0 + bcc;
    const float* Bsrc = (cglob < dout) ? Wn : Wr;
    int bcol = (cglob < dout) ? cglob : cglob - dout;

    unsigned long long acc[8][4];
    #pragma unroll
    for (int i = 0; i < 8; i++)
        #pragma unroll
        for (int q = 0; q < 4; q++) acc[i][q] = 0ULL;

    int gm = m0 + amm;
    float4 areg = make_float4(0.f, 0.f, 0.f, 0.f);
    if (gm < n) areg = *(const float4*)(A + (size_t)gm * 128 + akq);
    float4 breg = *(const float4*)(Bsrc + (size_t)bkk * dout + bcol);

    for (int k0 = 0;;) {
        As[akq + 0][amm] = areg.x;
        As[akq + 1][amm] = areg.y;
        As[akq + 2][amm] = areg.z;
        As[akq + 3][amm] = areg.w;
        *(float4*)&Bs[bkk][bcc] = breg;
        __syncthreads();
        int knext = k0 + 8;
        if (knext < 128) {
            if (gm < n) areg = *(const float4*)(A + (size_t)gm * 128 + knext + akq);
            breg = *(const float4*)(Bsrc + (size_t)(knext + bkk) * dout + bcol);
        }
        #pragma unroll
        for (int kk = 0; kk < 8; kk++) {
            float4 a0 = *(float4*)&As[kk][ty * 8];
            float4 a1 = *(float4*)&As[kk][ty * 8 + 4];
            ulonglong2 b0 = *(ulonglong2*)&Bs[kk][tx * 4];
            ulonglong2 b1 = *(ulonglong2*)&Bs[kk][64 + tx * 4];
            float av[8] = {a0.x, a0.y, a0.z, a0.w, a1.x, a1.y, a1.z, a1.w};
            #pragma unroll
            for (int i = 0; i < 8; i++) {
                unsigned long long ap = pack2(av[i], av[i]);
                acc[i][0] = fma2(ap, b0.x, acc[i][0]);
                acc[i][1] = fma2(ap, b0.y, acc[i][1]);
                acc[i][2] = fma2(ap, b1.x, acc[i][2]);
                acc[i][3] = fma2(ap, b1.y, acc[i][3]);
            }
        }
        k0 = knext;
        if (k0 >= 128) break;
        __syncthreads();
    }

    float bias[8];
    #pragma unroll
    for (int j = 0; j < 8; j++) {
        int c = c0 + (j < 4 ? tx * 4 + j : 64 + tx * 4 + (j - 4));
        bias[j] = (c < dout) ? 0.f : (cn[c - dout] + cr[c - dout]);
    }
    #pragma unroll
    for (int i = 0; i < 8; i++) {
        int m = m0 + ty * 8 + i;
        if (m >= n) continue;
        float v[8];
        unpack2(acc[i][0], v[0], v[1]);
        unpack2(acc[i][1], v[2], v[3]);
        unpack2(acc[i][2], v[4], v[5]);
        unpack2(acc[i][3], v[6], v[7]);
        float4 o0 = make_float4(v[0] + bias[0], v[1] + bias[1],
                                v[2] + bias[2], v[3] + bias[3]);
        float4 o1 = make_float4(v[4] + bias[4], v[5] + bias[5],
                                v[6] + bias[6], v[7] + bias[7]);
        *(float4*)(O + (size_t)m * W + c0 + tx * 4) = o0;
        *(float4*)(O + (size_t)m * W + c0 + 64 + tx * 4) = o1;
    }
}

// ---------------------------------------------------------------- aggregate
// warp per node: acc = sum_e w_e * P[src]; h = act(BN(acc + R[node])).
// Descriptor loads batched 4-deep for MLP.
template <int DO, bool DOBN>
__global__ void k_agg(const float* __restrict__ PR,
                      const float* __restrict__ gg, const float* __restrict__ bb,
                      const float* __restrict__ mm, const float* __restrict__ vv,
                      float* __restrict__ out, int n) {
    int w = (blockIdx.x * blockDim.x + threadIdx.x) >> 5;
    int lane = threadIdx.x & 31;
    if (w >= n) return;
    constexpr int V = DO / 32;
    constexpr int WI = 2 * DO;
    float acc[V];
    #pragma unroll
    for (int c = 0; c < V; c++) acc[c] = 0.f;

    int s = g_off[w], e2 = g_off[w + 1];
    int idx = s;
    for (; idx + 4 <= e2; idx += 4) {
        int2 v0 = __ldg(&g_csw[idx + 0]);
        int2 v1 = __ldg(&g_csw[idx + 1]);
        int2 v2 = __ldg(&g_csw[idx + 2]);
        int2 v3 = __ldg(&g_csw[idx + 3]);
        int2 vv4[4] = {v0, v1, v2, v3};
        #pragma unroll
        for (int u = 0; u < 4; u++) {
            float w2 = __int_as_float(vv4[u].y);
            const float* prow = PR + (size_t)vv4[u].x * WI;
            if constexpr (V == 4) {
                float4 p = ((const float4*)prow)[lane];
                acc[0] += w2 * p.x; acc[1] += w2 * p.y;
                acc[2] += w2 * p.z; acc[3] += w2 * p.w;
            } else {
                float2 p = ((const float2*)prow)[lane];
                acc[0] += w2 * p.x; acc[1] += w2 * p.y;
            }
        }
    }
    for (; idx < e2; idx++) {
        int2 v = __ldg(&g_csw[idx]);
        float w2 = __int_as_float(v.y);
        const float* prow = PR + (size_t)v.x * WI;
        if constexpr (V == 4) {
            float4 p = ((const float4*)prow)[lane];
            acc[0] += w2 * p.x; acc[1] += w2 * p.y;
            acc[2] += w2 * p.z; acc[3] += w2 * p.w;
        } else {
            float2 p = ((const float2*)prow)[lane];
            acc[0] += w2 * p.x; acc[1] += w2 * p.y;
        }
    }

    float r[V];
    const float* rrow = PR + (size_t)w * WI + DO;
    if constexpr (V == 4) {
        float4 rv = ((const float4*)rrow)[lane];
        r[0] = rv.x; r[1] = rv.y; r[2] = rv.z; r[3] = rv.w;
    } else {
        float2 rv = ((const float2*)rrow)[lane];
        r[0] = rv.x; r[1] = rv.y;
    }

    float h[V];
    #pragma unroll
    for (int c = 0; c < V; c++) {
        int d = lane * V + c;
        float hv = acc[c] + r[c];
        if (DOBN) {
            float sc = gg[d] * rsqrtf(vv[d] + 1e-5f);
            hv = (hv - mm[d]) * sc + bb[d];
            hv = fmaxf(hv, 0.f);
        }
        h[c] = hv;
    }
    if constexpr (V == 4) {
        ((float4*)(out + (size_t)w * DO))[lane] = make_float4(h[0], h[1], h[2], h[3]);
    } else {
        ((float2*)(out + (size_t)w * DO))[lane] = make_float2(h[0], h[1]);
    }
}

// ---------------------------------------------------------------- launch
extern "C" void kernel_launch(void* const* d_in, const int* in_sizes, int n_in,
                              void* d_out, int out_size) {
    const float* x   = (const float*)d_in[0];
    const void*  ei  = d_in[1];
    const float* Wn0 = (const float*)d_in[2];
    const float* cn0 = (const float*)d_in[3];
    const float* Wr0 = (const float*)d_in[4];
    const float* cr0 = (const float*)d_in[5];
    const float* Wn1 = (const float*)d_in[6];
    const float* cn1 = (const float*)d_in[7];
    const float* Wr1 = (const float*)d_in[8];
    const float* cr1 = (const float*)d_in[9];
    const float* Wn2 = (const float*)d_in[10];
    const float* cn2 = (const float*)d_in[11];
    const float* Wr2 = (const float*)d_in[12];
    const float* cr2 = (const float*)d_in[13];
    const float* g0  = (const float*)d_in[14];
    const float* b0  = (const float*)d_in[15];
    const float* m0  = (const float*)d_in[16];
    const float* v0  = (const float*)d_in[17];
    const float* g1  = (const float*)d_in[18];
    const float* b1  = (const float*)d_in[19];
    const float* m1  = (const float*)d_in[20];
    const float* v1  = (const float*)d_in[21];

    int n = in_sizes[0] / 128;
    int e = in_sizes[1] / 2;
    float* out = (float*)d_out;

    float *PR, *H;
    cudaGetSymbolAddress((void**)&PR, g_PR);
    cudaGetSymbolAddress((void**)&H, g_H);

    // lazy host-side stream/event setup (first call = eager correctness run,
    // so creation never happens during graph capture; no device allocations)
    static cudaStream_t s2 = nullptr;
    static cudaEvent_t ev0 = nullptr, ev1 = nullptr;
    if (!s2) {
        cudaStreamCreateWithFlags(&s2, cudaStreamNonBlocking);
        cudaEventCreateWithFlags(&ev0, cudaEventDisableTiming);
        cudaEventCreateWithFlags(&ev1, cudaEventDisableTiming);
    }

    int gx = (n + 127) / 128;

    // fork: gemm0 depends only on x -> overlap with edge-weight chain
    cudaEventRecord(ev0, 0);
    cudaStreamWaitEvent(s2, ev0, 0);
    k_gemm<<<dim3(gx, 2), 256, 0, s2>>>(x, Wn0, Wr0, cn0, cr0, PR, n, 128);
    cudaEventRecord(ev1, s2);

    // edge-weight chain on null stream
    k_detect<<<1, 256>>>(ei, e, n);
    k_init<<<(n + 255) / 256, 256>>>(n);
    k_norm<<<(n + 7) / 8, 256>>>(x, n);
    k_cnt<<<(e + 255) / 256, 256>>>(ei, e);
    k_scan<<<1, 1024>>>(n);
    k_place<<<(e + 255) / 256, 256>>>(ei, e);
    k_edge_csr<<<(n + 7) / 8, 256>>>(n);

    // join gemm0, then the serial layer chain
    cudaStreamWaitEvent(0, ev1, 0);
    k_agg<128, true><<<(n + 7) / 8, 256>>>(PR, g0, b0, m0, v0, H, n);
    k_gemm<<<dim3(gx, 2), 256>>>(H, Wn1, Wr1, cn1, cr1, PR, n, 128);
    k_agg<128, true><<<(n + 7) / 8, 256>>>(PR, g1, b1, m1, v1, H, n);
    k_gemm<<<dim3(gx, 1), 256>>>(H, Wn2, Wr2, cn2, cr2, PR, n, 64);
    k_agg<64, false><<<(n + 7) / 8, 256>>>(PR, g0, b0, m0, v0, out, n);
}

// round 4
// speedup vs baseline: 1.6028x; 1.1206x over previous
#include <cuda_runtime.h>
#include <cuda_fp16.h>
#include <cuda_bf16.h>

// ---------------------------------------------------------------------------
// SAGE_SimWeighted: 3-layer GNN, cosine-sim softmax edge weights.
// N=50000, E=1.6M, DIN=DH=128, DOUT=64.
//
// fp16 storage for gathered operands (xn, P) halves gather wavefronts;
// all accumulation fp32; R (self term) kept fp32.
//
//   null stream: detect -> init -> norm(x->xn fp16) -> cnt -> scan -> place
//                -> edge_csr (warp/node, dst row in regs, denom in-warp)
//                -> [join gemm0] agg0 -> gemm1 -> agg1 -> gemm2 -> agg2
//   stream 2   : gemm0 (depends only on x) overlapped with edge chain.
// ---------------------------------------------------------------------------

#define NMAX 50000
#define EMAX 1600000

__device__ __half g_xnh [(size_t)NMAX * 128];      // normalized x, fp16
__device__ int    g_cnt [NMAX];
__device__ int    g_off [NMAX + 1];
__device__ int    g_cur [NMAX];
__device__ int2   g_csw [EMAX];                    // {src, w bits}
__device__ __half g_Ph  [(size_t)NMAX * 128];      // P (neighbor term), fp16
__device__ float  g_R   [(size_t)NMAX * 128];      // R (self term), fp32
__device__ float  g_H   [(size_t)NMAX * 128];
__device__ int    g_is64;

// ---------------------------------------------------------------- f32x2 utils
__device__ __forceinline__ unsigned long long pack2(float lo, float hi) {
    unsigned long long r;
    asm("mov.b64 %0, {%1, %2};" : "=l"(r) : "f"(lo), "f"(hi));
    return r;
}
__device__ __forceinline__ unsigned long long fma2(unsigned long long a,
                                                   unsigned long long b,
                                                   unsigned long long c) {
    unsigned long long d;
    asm("fma.rn.f32x2 %0, %1, %2, %3;" : "=l"(d) : "l"(a), "l"(b), "l"(c));
    return d;
}
__device__ __forceinline__ void unpack2(unsigned long long v, float& lo, float& hi) {
    asm("mov.b64 {%0, %1}, %2;" : "=f"(lo), "=f"(hi) : "l"(v));
}

// ---------------------------------------------------------------- dtype probe
__global__ void k_detect(const void* ei, int e, int n) {
    __shared__ int bad;
    if (threadIdx.x == 0) bad = 0;
    __syncthreads();
    const long long* p = (const long long*)ei;
    int lim = e < 2048 ? e : 2048;
    for (int i = threadIdx.x; i < lim; i += blockDim.x) {
        long long v = p[i];
        if (v < 0 || v >= (long long)n) bad = 1;
    }
    __syncthreads();
    if (threadIdx.x == 0) g_is64 = bad ? 0 : 1;
}

__device__ __forceinline__ int load_idx(const void* ei, long long pos) {
    if (g_is64) return (int)((const long long*)ei)[pos];
    return ((const int*)ei)[pos];
}

// ---------------------------------------------------------------- init
__global__ void k_init(int n) {
    int i = blockIdx.x * blockDim.x + threadIdx.x;
    if (i < n) g_cnt[i] = 0;
}

// ---------------------------------------------------------------- normalize x
__global__ void k_norm(const float* __restrict__ x, int n) {
    int w = (blockIdx.x * blockDim.x + threadIdx.x) >> 5;
    int lane = threadIdx.x & 31;
    if (w >= n) return;
    float4 a = ((const float4*)x)[(size_t)w * 32 + lane];
    float s = a.x * a.x + a.y * a.y + a.z * a.z + a.w * a.w;
    #pragma unroll
    for (int o = 16; o; o >>= 1) s += __shfl_xor_sync(0xffffffffu, s, o);
    float inv = 1.f / (sqrtf(s) + 1e-12f);
    half2 h0 = __floats2half2_rn(a.x * inv, a.y * inv);
    half2 h1 = __floats2half2_rn(a.z * inv, a.w * inv);
    uint2 q;
    q.x = *(unsigned*)&h0; q.y = *(unsigned*)&h1;
    ((uint2*)g_xnh)[(size_t)w * 32 + lane] = q;
}

// ---------------------------------------------------------------- degree cnt
__global__ void k_cnt(const void* __restrict__ ei, int e) {
    int i = blockIdx.x * blockDim.x + threadIdx.x;
    if (i >= e) return;
    int d = load_idx(ei, (long long)e + i);
    atomicAdd(&g_cnt[d], 1);
}

// ---------------------------------------------------------------- scan (1 blk)
__global__ void k_scan(int n) {
    __shared__ int warp_excl[32];
    __shared__ int s_tot;
    __shared__ int s_carry;
    int t = threadIdx.x, lane = t & 31, wid = t >> 5;
    if (t == 0) s_carry = 0;
    __syncthreads();
    for (int base = 0; base < n; base += 1024) {
        int i = base + t;
        int v = (i < n) ? g_cnt[i] : 0;
        int x = v;
        #pragma unroll
        for (int o = 1; o < 32; o <<= 1) {
            int y = __shfl_up_sync(0xffffffffu, x, o);
            if (lane >= o) x += y;
        }
        if (lane == 31) warp_excl[wid] = x;
        __syncthreads();
        if (wid == 0) {
            int wv = warp_excl[lane];
            int xx = wv;
            #pragma unroll
            for (int o = 1; o < 32; o <<= 1) {
                int y = __shfl_up_sync(0xffffffffu, xx, o);
                if (lane >= o) xx += y;
            }
            if (lane == 31) s_tot = xx;
            warp_excl[lane] = xx - wv;
        }
        __syncthreads();
        int excl = s_carry + warp_excl[wid] + (x - v);
        if (i < n) { g_off[i] = excl; g_cur[i] = excl; }
        __syncthreads();
        if (t == 0) s_carry += s_tot;
        __syncthreads();
    }
    if (t == 0) g_off[n] = s_carry;
}

// ---------------------------------------------------------------- place srcs
__global__ void k_place(const void* __restrict__ ei, int e) {
    int i = blockIdx.x * blockDim.x + threadIdx.x;
    if (i >= e) return;
    int s = load_idx(ei, i);
    int d = load_idx(ei, (long long)e + i);
    int pos = atomicAdd(&g_cur[d], 1);
    ((int*)g_csw)[2 * pos] = s;
}

// ---------------------------------------------------------------- edge weights
// warp per dst node; 4 groups of 8 lanes; group g handles edges g, g+4, ...
// fp16 rows: lane t loads uint4 (8 half) at t*16B + j*128B, j=0,1 ->
// one 128B line per 8-lane group per instruction (2 wavefronts/edge).
__global__ void k_edge_csr(int n) {
    int w = (blockIdx.x * blockDim.x + threadIdx.x) >> 5;
    int lane = threadIdx.x & 31;
    if (w >= n) return;
    int g = lane >> 3, t = lane & 7;
    unsigned gmask = 0xFFu << (g * 8);
    int s0 = g_off[w], e0 = g_off[w + 1];
    int nE = e0 - s0;
    if (nE == 0) return;

    // dst row (16 half per lane) converted once to fp32
    float dreg[16];
    const uint4* dp = (const uint4*)(g_xnh + (size_t)w * 128);
    #pragma unroll
    for (int j = 0; j < 2; j++) {
        uint4 q = dp[t + j * 8];
        const half2* h = (const half2*)&q;
        #pragma unroll
        for (int c = 0; c < 4; c++) {
            float2 f = __half22float2(h[c]);
            dreg[j * 8 + c * 2 + 0] = f.x;
            dreg[j * 8 + c * 2 + 1] = f.y;
        }
    }

    float dsum = 0.f;
    for (int i = g; i < nE; i += 4) {
        int pos = s0 + i;
        int sidx = ((const int*)g_csw)[2 * pos];     // broadcast within group
        const uint4* sp = (const uint4*)(g_xnh + (size_t)sidx * 128);
        float dpacc = 0.f;
        #pragma unroll
        for (int j = 0; j < 2; j++) {
            uint4 q = sp[t + j * 8];
            const half2* h = (const half2*)&q;
            #pragma unroll
            for (int c = 0; c < 4; c++) {
                float2 f = __half22float2(h[c]);
                dpacc += f.x * dreg[j * 8 + c * 2 + 0]
                       + f.y * dreg[j * 8 + c * 2 + 1];
            }
        }
        dpacc += __shfl_xor_sync(gmask, dpacc, 4);
        dpacc += __shfl_xor_sync(gmask, dpacc, 2);
        dpacc += __shfl_xor_sync(gmask, dpacc, 1);
        if (t == 0) {
            float ev = __expf(dpacc * 2.0f - 2.0f);  // /TAU(0.5), shift 2
            ((int*)g_csw)[2 * pos + 1] = __float_as_int(ev);
            dsum += ev;
        }
    }
    if (t != 0) dsum = 0.f;
    __syncwarp();
    dsum += __shfl_xor_sync(0xffffffffu, dsum, 8);
    dsum += __shfl_xor_sync(0xffffffffu, dsum, 16);
    float inv = 1.f / (__shfl_sync(0xffffffffu, dsum, 0) + 1e-16f);
    for (int i = lane; i < nE; i += 32) {
        int q = 2 * (s0 + i) + 1;
        float ev = __int_as_float(((int*)g_csw)[q]);
        ((int*)g_csw)[q] = __float_as_int(ev * inv);
    }
}

// ---------------------------------------------------------------- fused GEMM
// [P | R] = A[n x 128] @ [Wn | Wr]; P stored fp16 (no bias), R fp32 (+cn+cr).
// 128x128 block tile, BK=8, 256 threads, 8x8 micro-tile, f32x2 FFMA2.
__global__ void __launch_bounds__(256, 2)
k_gemm(const float* __restrict__ A,
       const float* __restrict__ Wn, const float* __restrict__ Wr,
       const float* __restrict__ cn, const float* __restrict__ cr,
       __half* __restrict__ Ph, float* __restrict__ Rf, int n, int dout) {
    __shared__ float As[8][132];
    __shared__ float Bs[8][128];
    int tid = threadIdx.x;
    int tx = tid & 15, ty = tid >> 4;
    int m0 = blockIdx.x * 128, c0 = blockIdx.y * 128;

    int amm = tid >> 1;
    int akq = (tid & 1) * 4;
    int bkk = tid >> 5;
    int bcc = (tid & 31) * 4;

    int cglob = c0 + bcc;
    const float* Bsrc = (cglob < dout) ? Wn : Wr;
    int bcol = (cglob < dout) ? cglob : cglob - dout;

    unsigned long long acc[8][4];
    #pragma unroll
    for (int i = 0; i < 8; i++)
        #pragma unroll
        for (int q = 0; q < 4; q++) acc[i][q] = 0ULL;

    int gm = m0 + amm;
    float4 areg = make_float4(0.f, 0.f, 0.f, 0.f);
    if (gm < n) areg = *(const float4*)(A + (size_t)gm * 128 + akq);
    float4 breg = *(const float4*)(Bsrc + (size_t)bkk * dout + bcol);

    for (int k0 = 0;;) {
        As[akq + 0][amm] = areg.x;
        As[akq + 1][amm] = areg.y;
        As[akq + 2][amm] = areg.z;
        As[akq + 3][amm] = areg.w;
        *(float4*)&Bs[bkk][bcc] = breg;
        __syncthreads();
        int knext = k0 + 8;
        if (knext < 128) {
            if (gm < n) areg = *(const float4*)(A + (size_t)gm * 128 + knext + akq);
            breg = *(const float4*)(Bsrc + (size_t)(knext + bkk) * dout + bcol);
        }
        #pragma unroll
        for (int kk = 0; kk < 8; kk++) {
            float4 a0 = *(float4*)&As[kk][ty * 8];
            float4 a1 = *(float4*)&As[kk][ty * 8 + 4];
            ulonglong2 b0 = *(ulonglong2*)&Bs[kk][tx * 4];
            ulonglong2 b1 = *(ulonglong2*)&Bs[kk][64 + tx * 4];
            float av[8] = {a0.x, a0.y, a0.z, a0.w, a1.x, a1.y, a1.z, a1.w};
            #pragma unroll
            for (int i = 0; i < 8; i++) {
                unsigned long long ap = pack2(av[i], av[i]);
                acc[i][0] = fma2(ap, b0.x, acc[i][0]);
                acc[i][1] = fma2(ap, b0.y, acc[i][1]);
                acc[i][2] = fma2(ap, b1.x, acc[i][2]);
                acc[i][3] = fma2(ap, b1.y, acc[i][3]);
            }
        }
        k0 = knext;
        if (k0 >= 128) break;
        __syncthreads();
    }

    int cA = c0 + tx * 4;        // chunk A columns (4)
    int cB = c0 + 64 + tx * 4;   // chunk B columns (4)
    float biasA[4], biasB[4];
    #pragma unroll
    for (int j = 0; j < 4; j++) {
        biasA[j] = (cA + j < dout) ? 0.f : (cn[cA + j - dout] + cr[cA + j - dout]);
        biasB[j] = (cB + j < dout) ? 0.f : (cn[cB + j - dout] + cr[cB + j - dout]);
    }
    #pragma unroll
    for (int i = 0; i < 8; i++) {
        int m = m0 + ty * 8 + i;
        if (m >= n) continue;
        float v[8];
        unpack2(acc[i][0], v[0], v[1]);
        unpack2(acc[i][1], v[2], v[3]);
        unpack2(acc[i][2], v[4], v[5]);
        unpack2(acc[i][3], v[6], v[7]);
        if (cA < dout) {   // P chunk -> fp16
            half2 h0 = __floats2half2_rn(v[0], v[1]);
            half2 h1 = __floats2half2_rn(v[2], v[3]);
            uint2 q; q.x = *(unsigned*)&h0; q.y = *(unsigned*)&h1;
            *(uint2*)(Ph + (size_t)m * dout + cA) = q;
        } else {           // R chunk -> fp32 + bias
            float4 o = make_float4(v[0] + biasA[0], v[1] + biasA[1],
                                   v[2] + biasA[2], v[3] + biasA[3]);
            *(float4*)(Rf + (size_t)m * dout + cA - dout) = o;
        }
        if (cB < dout) {
            half2 h0 = __floats2half2_rn(v[4], v[5]);
            half2 h1 = __floats2half2_rn(v[6], v[7]);
            uint2 q; q.x = *(unsigned*)&h0; q.y = *(unsigned*)&h1;
            *(uint2*)(Ph + (size_t)m * dout + cB) = q;
        } else {
            float4 o = make_float4(v[4] + biasB[0], v[5] + biasB[1],
                                   v[6] + biasB[2], v[7] + biasB[3]);
            *(float4*)(Rf + (size_t)m * dout + cB - dout) = o;
        }
    }
}

// ---------------------------------------------------------------- aggregate
// warp per node: acc = sum_e w_e * Ph[src] (fp16 gather, fp32 accumulate);
// h = act(BN(acc + R[node])). Descriptor loads batched 4-deep for MLP.
template <int DO, bool DOBN>
__global__ void k_agg(const __half* __restrict__ Ph, const float* __restrict__ Rf,
                      const float* __restrict__ gg, const float* __restrict__ bb,
                      const float* __restrict__ mm, const float* __restrict__ vv,
                      float* __restrict__ out, int n) {
    int w = (blockIdx.x * blockDim.x + threadIdx.x) >> 5;
    int lane = threadIdx.x & 31;
    if (w >= n) return;
    constexpr int V = DO / 32;      // 4 or 2 cols per lane
    float acc[V];
    #pragma unroll
    for (int c = 0; c < V; c++) acc[c] = 0.f;

    int s = g_off[w], e2 = g_off[w + 1];

    auto body = [&](int2 v) {
        float w2 = __int_as_float(v.y);
        const __half* prow = Ph + (size_t)v.x * DO;
        if constexpr (V == 4) {
            uint2 q = ((const uint2*)prow)[lane];     // 4 half
            float2 p01 = __half22float2(*(const half2*)&q.x);
            float2 p23 = __half22float2(*(const half2*)&q.y);
            acc[0] += w2 * p01.x; acc[1] += w2 * p01.y;
            acc[2] += w2 * p23.x; acc[3] += w2 * p23.y;
        } else {
            unsigned q = ((const unsigned*)prow)[lane]; // 2 half
            float2 p = __half22float2(*(const half2*)&q);
            acc[0] += w2 * p.x; acc[1] += w2 * p.y;
        }
    };

    int idx = s;
    for (; idx + 4 <= e2; idx += 4) {
        int2 v0 = __ldg(&g_csw[idx + 0]);
        int2 v1 = __ldg(&g_csw[idx + 1]);
        int2 v2 = __ldg(&g_csw[idx + 2]);
        int2 v3 = __ldg(&g_csw[idx + 3]);
        body(v0); body(v1); body(v2); body(v3);
    }
    for (; idx < e2; idx++) body(__ldg(&g_csw[idx]));

    float r[V];
    const float* rrow = Rf + (size_t)w * DO;
    if constexpr (V == 4) {
        float4 rv = ((const float4*)rrow)[lane];
        r[0] = rv.x; r[1] = rv.y; r[2] = rv.z; r[3] = rv.w;
    } else {
        float2 rv = ((const float2*)rrow)[lane];
        r[0] = rv.x; r[1] = rv.y;
    }

    float h[V];
    #pragma unroll
    for (int c = 0; c < V; c++) {
        int d = lane * V + c;
        float hv = acc[c] + r[c];
        if (DOBN) {
            float sc = gg[d] * rsqrtf(vv[d] + 1e-5f);
            hv = (hv - mm[d]) * sc + bb[d];
            hv = fmaxf(hv, 0.f);
        }
        h[c] = hv;
    }
    if constexpr (V == 4) {
        ((float4*)(out + (size_t)w * DO))[lane] = make_float4(h[0], h[1], h[2], h[3]);
    } else {
        ((float2*)(out + (size_t)w * DO))[lane] = make_float2(h[0], h[1]);
    }
}

// ---------------------------------------------------------------- launch
extern "C" void kernel_launch(void* const* d_in, const int* in_sizes, int n_in,
                              void* d_out, int out_size) {
    const float* x   = (const float*)d_in[0];
    const void*  ei  = d_in[1];
    const float* Wn0 = (const float*)d_in[2];
    const float* cn0 = (const float*)d_in[3];
    const float* Wr0 = (const float*)d_in[4];
    const float* cr0 = (const float*)d_in[5];
    const float* Wn1 = (const float*)d_in[6];
    const float* cn1 = (const float*)d_in[7];
    const float* Wr1 = (const float*)d_in[8];
    const float* cr1 = (const float*)d_in[9];
    const float* Wn2 = (const float*)d_in[10];
    const float* cn2 = (const float*)d_in[11];
    const float* Wr2 = (const float*)d_in[12];
    const float* cr2 = (const float*)d_in[13];
    const float* g0  = (const float*)d_in[14];
    const float* b0  = (const float*)d_in[15];
    const float* m0  = (const float*)d_in[16];
    const float* v0  = (const float*)d_in[17];
    const float* g1  = (const float*)d_in[18];
    const float* b1  = (const float*)d_in[19];
    const float* m1  = (const float*)d_in[20];
    const float* v1  = (const float*)d_in[21];

    int n = in_sizes[0] / 128;
    int e = in_sizes[1] / 2;
    float* out = (float*)d_out;

    __half* Ph; float *Rf, *H;
    cudaGetSymbolAddress((void**)&Ph, g_Ph);
    cudaGetSymbolAddress((void**)&Rf, g_R);
    cudaGetSymbolAddress((void**)&H, g_H);

    static cudaStream_t s2 = nullptr;
    static cudaEvent_t ev0 = nullptr, ev1 = nullptr;
    if (!s2) {
        cudaStreamCreateWithFlags(&s2, cudaStreamNonBlocking);
        cudaEventCreateWithFlags(&ev0, cudaEventDisableTiming);
        cudaEventCreateWithFlags(&ev1, cudaEventDisableTiming);
    }

    int gx = (n + 127) / 128;

    // fork: gemm0 depends only on x -> overlap with edge-weight chain
    cudaEventRecord(ev0, 0);
    cudaStreamWaitEvent(s2, ev0, 0);
    k_gemm<<<dim3(gx, 2), 256, 0, s2>>>(x, Wn0, Wr0, cn0, cr0, Ph, Rf, n, 128);
    cudaEventRecord(ev1, s2);

    // edge-weight chain on null stream
    k_detect<<<1, 256>>>(ei, e, n);
    k_init<<<(n + 255) / 256, 256>>>(n);
    k_norm<<<(n + 7) / 8, 256>>>(x, n);
    k_cnt<<<(e + 255) / 256, 256>>>(ei, e);
    k_scan<<<1, 1024>>>(n);
    k_place<<<(e + 255) / 256, 256>>>(ei, e);
    k_edge_csr<<<(n + 7) / 8, 256>>>(n);

    // join gemm0, then the serial layer chain
    cudaStreamWaitEvent(0, ev1, 0);
    k_agg<128, true><<<(n + 7) / 8, 256>>>(Ph, Rf, g0, b0, m0, v0, H, n);
    k_gemm<<<dim3(gx, 2), 256>>>(H, Wn1, Wr1, cn1, cr1, Ph, Rf, n, 128);
    k_agg<128, true><<<(n + 7) / 8, 256>>>(Ph, Rf, g1, b1, m1, v1, H, n);
    k_gemm<<<dim3(gx, 1), 256>>>(H, Wn2, Wr2, cn2, cr2, Ph, Rf, n, 64);
    k_agg<64, false><<<(n + 7) / 8, 256>>>(Ph, Rf, g0, b0, m0, v0, out, n);
}

// round 5
// speedup vs baseline: 2.2065x; 1.3766x over previous
#include <cuda_runtime.h>
#include <cuda_fp16.h>
#include <cuda_bf16.h>

// ---------------------------------------------------------------------------
// SAGE_SimWeighted: 3-layer GNN, cosine-sim softmax edge weights.
// N=50000, E=1.6M, DIN=DH=128, DOUT=64.
//
// fp16 storage for ALL gathered/GEMM operands (xn, x, H, P, W), fp32 accum.
// GEMMs on tensor cores via mma.sync.m16n8k16.
//
//   stream0: detect -> init -> cnt -> scan -> place -> [join s2]
//            edge_csr -> agg0 -> gemm1 -> agg1 -> gemm2 -> agg2
//   s2     : x2h -> prepw(0,1,2) -> gemm0 -> norm        (overlapped)
// ---------------------------------------------------------------------------

#define NMAX 50000
#define EMAX 1600000

__device__ __half g_xh  [(size_t)NMAX * 128];      // x cast fp16 (gemm0 input)
__device__ __half g_xnh [(size_t)NMAX * 128];      // normalized x, fp16
__device__ __half g_Hh  [(size_t)NMAX * 128];      // hidden, fp16
__device__ __half g_Ph  [(size_t)NMAX * 128];      // P (neighbor term), fp16
__device__ float  g_R   [(size_t)NMAX * 128];      // R (self term), fp32
__device__ __half g_W0t [256 * 128];               // [Wn0|Wr0]^T fp16
__device__ __half g_W1t [256 * 128];
__device__ __half g_W2t [128 * 128];
__device__ int    g_cnt [NMAX];
__device__ int    g_off [NMAX + 1];
__device__ int    g_cur [NMAX];
__device__ int2   g_csw [EMAX];                    // {src, w bits}
__device__ int    g_is64;

// ---------------------------------------------------------------- mma wrapper
__device__ __forceinline__ void mma16816(float* c, const unsigned* a,
                                         unsigned b0, unsigned b1) {
    asm volatile(
        "mma.sync.aligned.m16n8k16.row.col.f32.f16.f16.f32 "
        "{%0,%1,%2,%3}, {%4,%5,%6,%7}, {%8,%9}, {%0,%1,%2,%3};"
        : "+f"(c[0]), "+f"(c[1]), "+f"(c[2]), "+f"(c[3])
        : "r"(a[0]), "r"(a[1]), "r"(a[2]), "r"(a[3]), "r"(b0), "r"(b1));
}

// ---------------------------------------------------------------- dtype probe
__global__ void k_detect(const void* ei, int e, int n) {
    __shared__ int bad;
    if (threadIdx.x == 0) bad = 0;
    __syncthreads();
    const long long* p = (const long long*)ei;
    int lim = e < 2048 ? e : 2048;
    for (int i = threadIdx.x; i < lim; i += blockDim.x) {
        long long v = p[i];
        if (v < 0 || v >= (long long)n) bad = 1;
    }
    __syncthreads();
    if (threadIdx.x == 0) g_is64 = bad ? 0 : 1;
}

__device__ __forceinline__ int load_idx(const void* ei, long long pos) {
    if (g_is64) return (int)((const long long*)ei)[pos];
    return ((const int*)ei)[pos];
}

// ---------------------------------------------------------------- init
__global__ void k_init(int n) {
    int i = blockIdx.x * blockDim.x + threadIdx.x;
    if (i < n) g_cnt[i] = 0;
}

// ---------------------------------------------------------------- x -> fp16
__global__ void k_x2h(const float* __restrict__ x, int n) {
    int i = blockIdx.x * blockDim.x + threadIdx.x;   // one uint4 (8 half)
    if (i >= n * 16) return;
    float4 a = ((const float4*)x)[i * 2];
    float4 b = ((const float4*)x)[i * 2 + 1];
    half2 h0 = __floats2half2_rn(a.x, a.y);
    half2 h1 = __floats2half2_rn(a.z, a.w);
    half2 h2 = __floats2half2_rn(b.x, b.y);
    half2 h3 = __floats2half2_rn(b.z, b.w);
    uint4 q;
    q.x = *(unsigned*)&h0; q.y = *(unsigned*)&h1;
    q.z = *(unsigned*)&h2; q.w = *(unsigned*)&h3;
    ((uint4*)g_xh)[i] = q;
}

// ---------------------------------------------------------------- weight prep
// Wt[j][k] = (j < dout ? Wn[k][j] : Wr[k][j-dout]) as fp16; Wt is [2*dout x 128]
__global__ void k_prepw(const float* __restrict__ Wn, const float* __restrict__ Wr,
                        __half* __restrict__ Wt, int dout) {
    int i = blockIdx.x * blockDim.x + threadIdx.x;
    if (i >= 2 * dout * 128) return;
    int j = i >> 7, k = i & 127;
    float v = (j < dout) ? Wn[k * dout + j] : Wr[k * dout + (j - dout)];
    Wt[j * 128 + k] = __float2half(v);
}

// ---------------------------------------------------------------- normalize x
__global__ void k_norm(const float* __restrict__ x, int n) {
    int w = (blockIdx.x * blockDim.x + threadIdx.x) >> 5;
    int lane = threadIdx.x & 31;
    if (w >= n) return;
    float4 a = ((const float4*)x)[(size_t)w * 32 + lane];
    float s = a.x * a.x + a.y * a.y + a.z * a.z + a.w * a.w;
    #pragma unroll
    for (int o = 16; o; o >>= 1) s += __shfl_xor_sync(0xffffffffu, s, o);
    float inv = 1.f / (sqrtf(s) + 1e-12f);
    half2 h0 = __floats2half2_rn(a.x * inv, a.y * inv);
    half2 h1 = __floats2half2_rn(a.z * inv, a.w * inv);
    uint2 q;
    q.x = *(unsigned*)&h0; q.y = *(unsigned*)&h1;
    ((uint2*)g_xnh)[(size_t)w * 32 + lane] = q;
}

// ---------------------------------------------------------------- degree cnt
__global__ void k_cnt(const void* __restrict__ ei, int e) {
    int i = blockIdx.x * blockDim.x + threadIdx.x;
    if (i >= e) return;
    int d = load_idx(ei, (long long)e + i);
    atomicAdd(&g_cnt[d], 1);
}

// ---------------------------------------------------------------- scan (1 blk)
__global__ void k_scan(int n) {
    __shared__ int warp_excl[32];
    __shared__ int s_tot;
    __shared__ int s_carry;
    int t = threadIdx.x, lane = t & 31, wid = t >> 5;
    if (t == 0) s_carry = 0;
    __syncthreads();
    for (int base = 0; base < n; base += 1024) {
        int i = base + t;
        int v = (i < n) ? g_cnt[i] : 0;
        int x = v;
        #pragma unroll
        for (int o = 1; o < 32; o <<= 1) {
            int y = __shfl_up_sync(0xffffffffu, x, o);
            if (lane >= o) x += y;
        }
        if (lane == 31) warp_excl[wid] = x;
        __syncthreads();
        if (wid == 0) {
            int wv = warp_excl[lane];
            int xx = wv;
            #pragma unroll
            for (int o = 1; o < 32; o <<= 1) {
                int y = __shfl_up_sync(0xffffffffu, xx, o);
                if (lane >= o) xx += y;
            }
            if (lane == 31) s_tot = xx;
            warp_excl[lane] = xx - wv;
        }
        __syncthreads();
        int excl = s_carry + warp_excl[wid] + (x - v);
        if (i < n) { g_off[i] = excl; g_cur[i] = excl; }
        __syncthreads();
        if (t == 0) s_carry += s_tot;
        __syncthreads();
    }
    if (t == 0) g_off[n] = s_carry;
}

// ---------------------------------------------------------------- place srcs
__global__ void k_place(const void* __restrict__ ei, int e) {
    int i = blockIdx.x * blockDim.x + threadIdx.x;
    if (i >= e) return;
    int s = load_idx(ei, i);
    int d = load_idx(ei, (long long)e + i);
    int pos = atomicAdd(&g_cur[d], 1);
    ((int*)g_csw)[2 * pos] = s;
}

// ---------------------------------------------------------------- edge weights
// warp per dst node; 4 groups of 8 lanes; group g handles edges g, g+4, ...
__global__ void k_edge_csr(int n) {
    int w = (blockIdx.x * blockDim.x + threadIdx.x) >> 5;
    int lane = threadIdx.x & 31;
    if (w >= n) return;
    int g = lane >> 3, t = lane & 7;
    unsigned gmask = 0xFFu << (g * 8);
    int s0 = g_off[w], e0 = g_off[w + 1];
    int nE = e0 - s0;
    if (nE == 0) return;

    float dreg[16];
    const uint4* dp = (const uint4*)(g_xnh + (size_t)w * 128);
    #pragma unroll
    for (int j = 0; j < 2; j++) {
        uint4 q = dp[t + j * 8];
        const half2* h = (const half2*)&q;
        #pragma unroll
        for (int c = 0; c < 4; c++) {
            float2 f = __half22float2(h[c]);
            dreg[j * 8 + c * 2 + 0] = f.x;
            dreg[j * 8 + c * 2 + 1] = f.y;
        }
    }

    float dsum = 0.f;
    for (int i = g; i < nE; i += 4) {
        int pos = s0 + i;
        int sidx = ((const int*)g_csw)[2 * pos];
        const uint4* sp = (const uint4*)(g_xnh + (size_t)sidx * 128);
        float dpacc = 0.f;
        #pragma unroll
        for (int j = 0; j < 2; j++) {
            uint4 q = sp[t + j * 8];
            const half2* h = (const half2*)&q;
            #pragma unroll
            for (int c = 0; c < 4; c++) {
                float2 f = __half22float2(h[c]);
                dpacc += f.x * dreg[j * 8 + c * 2 + 0]
                       + f.y * dreg[j * 8 + c * 2 + 1];
            }
        }
        dpacc += __shfl_xor_sync(gmask, dpacc, 4);
        dpacc += __shfl_xor_sync(gmask, dpacc, 2);
        dpacc += __shfl_xor_sync(gmask, dpacc, 1);
        if (t == 0) {
            float ev = __expf(dpacc * 2.0f - 2.0f);  // /TAU(0.5), shift 2
            ((int*)g_csw)[2 * pos + 1] = __float_as_int(ev);
            dsum += ev;
        }
    }
    if (t != 0) dsum = 0.f;
    __syncwarp();
    dsum += __shfl_xor_sync(0xffffffffu, dsum, 8);
    dsum += __shfl_xor_sync(0xffffffffu, dsum, 16);
    float inv = 1.f / (__shfl_sync(0xffffffffu, dsum, 0) + 1e-16f);
    for (int i = lane; i < nE; i += 32) {
        int q = 2 * (s0 + i) + 1;
        float ev = __int_as_float(((int*)g_csw)[q]);
        ((int*)g_csw)[q] = __float_as_int(ev * inv);
    }
}

// ---------------------------------------------------------------- tensor GEMM
// C[n x W2] = A[n x 128] (fp16) @ Wt^T (Wt is [W2 x 128] fp16).
// Block 128x128, 8 warps (4x2), warp tile 32x64, mma.m16n8k16, fp32 accum.
// Epilogue: cols < dout -> Ph fp16 (no bias); cols >= dout -> Rf fp32 + cn+cr.
#define SSTR 24   // smem row stride in halves (48B): conflict-free frags
__global__ void __launch_bounds__(256)
k_hgemm(const __half* __restrict__ A, const __half* __restrict__ Bt,
        const float* __restrict__ cn, const float* __restrict__ cr,
        __half* __restrict__ Ph, float* __restrict__ Rf, int n, int dout) {
    __shared__ __half As[2][128 * SSTR];
    __shared__ __half Bs[2][128 * SSTR];
    int tid = threadIdx.x;
    int m0 = blockIdx.x * 128, c0 = blockIdx.y * 128;

    int lr = tid >> 1, seg = tid & 1;
    bool aok = (m0 + lr) < n;
    const __half* Arow = A + (size_t)(m0 + lr) * 128 + seg * 8;
    const __half* Brow = Bt + (size_t)(c0 + lr) * 128 + seg * 8;
    int sidx = lr * SSTR + seg * 8;

    float acc[16][4];
    #pragma unroll
    for (int i = 0; i < 16; i++)
        #pragma unroll
        for (int q = 0; q < 4; q++) acc[i][q] = 0.f;

    uint4 aR = make_uint4(0, 0, 0, 0), bR;
    if (aok) aR = *(const uint4*)Arow;
    bR = *(const uint4*)Brow;
    *(uint4*)&As[0][sidx] = aR;
    *(uint4*)&Bs[0][sidx] = bR;
    __syncthreads();

    int wid = tid >> 5, lane = tid & 31;
    int wm = wid >> 1, wn = wid & 1;
    int qr = lane >> 2, qc = lane & 3;

    #pragma unroll
    for (int s = 0; s < 8; s++) {
        int cur = s & 1;
        if (s < 7) {
            aR = make_uint4(0, 0, 0, 0);
            if (aok) aR = *(const uint4*)(Arow + (s + 1) * 16);
            bR = *(const uint4*)(Brow + (s + 1) * 16);
        }
        unsigned afr[2][4];
        #pragma unroll
        for (int mi = 0; mi < 2; mi++) {
            const __half* base = &As[cur][(wm * 32 + mi * 16 + qr) * SSTR + qc * 2];
            afr[mi][0] = *(const unsigned*)(base);
            afr[mi][1] = *(const unsigned*)(base + 8 * SSTR);   // row +8
            afr[mi][2] = *(const unsigned*)(base + 8);          // k +8
            afr[mi][3] = *(const unsigned*)(base + 8 * SSTR + 8);
        }
        #pragma unroll
        for (int ni = 0; ni < 8; ni++) {
            const __half* bb = &Bs[cur][(wn * 64 + ni * 8 + qr) * SSTR + qc * 2];
            unsigned b0 = *(const unsigned*)bb;
            unsigned b1 = *(const unsigned*)(bb + 8);
            mma16816(acc[ni], afr[0], b0, b1);
            mma16816(acc[8 + ni], afr[1], b0, b1);
        }
        if (s < 7) {
            *(uint4*)&As[cur ^ 1][sidx] = aR;
            *(uint4*)&Bs[cur ^ 1][sidx] = bR;
            __syncthreads();
        }
    }

    #pragma unroll
    for (int mi = 0; mi < 2; mi++) {
        int rA = m0 + wm * 32 + mi * 16 + qr;
        int rB = rA + 8;
        #pragma unroll
        for (int ni = 0; ni < 8; ni++) {
            float* c = acc[mi * 8 + ni];
            int gc = c0 + wn * 64 + ni * 8 + qc * 2;
            if (gc < dout) {
                half2 hA = __floats2half2_rn(c[0], c[1]);
                half2 hB = __floats2half2_rn(c[2], c[3]);
                if (rA < n) *(half2*)(Ph + (size_t)rA * dout + gc) = hA;
                if (rB < n) *(half2*)(Ph + (size_t)rB * dout + gc) = hB;
            } else {
                int rc = gc - dout;
                float bx = cn[rc] + cr[rc];
                float by = cn[rc + 1] + cr[rc + 1];
                if (rA < n) *(float2*)(Rf + (size_t)rA * dout + rc)
                                = make_float2(c[0] + bx, c[1] + by);
                if (rB < n) *(float2*)(Rf + (size_t)rB * dout + rc)
                                = make_float2(c[2] + bx, c[3] + by);
            }
        }
    }
}

// ---------------------------------------------------------------- aggregate
// warp per node: acc = sum_e w_e * Ph[src] (fp16 gather, fp32 accumulate);
// h = act(BN(acc + R[node])). HOUT: write fp16 (next GEMM input) else fp32.
template <int DO, bool DOBN, bool HOUT>
__global__ void k_agg(const __half* __restrict__ Ph, const float* __restrict__ Rf,
                      const float* __restrict__ gg, const float* __restrict__ bb,
                      const float* __restrict__ mm, const float* __restrict__ vv,
                      void* __restrict__ outv, int n) {
    int w = (blockIdx.x * blockDim.x + threadIdx.x) >> 5;
    int lane = threadIdx.x & 31;
    if (w >= n) return;
    constexpr int V = DO / 32;
    float acc[V];
    #pragma unroll
    for (int c = 0; c < V; c++) acc[c] = 0.f;

    int s = g_off[w], e2 = g_off[w + 1];

    auto body = [&](int2 v) {
        float w2 = __int_as_float(v.y);
        const __half* prow = Ph + (size_t)v.x * DO;
        if constexpr (V == 4) {
            uint2 q = ((const uint2*)prow)[lane];
            float2 p01 = __half22float2(*(const half2*)&q.x);
            float2 p23 = __half22float2(*(const half2*)&q.y);
            acc[0] += w2 * p01.x; acc[1] += w2 * p01.y;
            acc[2] += w2 * p23.x; acc[3] += w2 * p23.y;
        } else {
            unsigned q = ((const unsigned*)prow)[lane];
            float2 p = __half22float2(*(const half2*)&q);
            acc[0] += w2 * p.x; acc[1] += w2 * p.y;
        }
    };

    int idx = s;
    for (; idx + 4 <= e2; idx += 4) {
        int2 v0 = __ldg(&g_csw[idx + 0]);
        int2 v1 = __ldg(&g_csw[idx + 1]);
        int2 v2 = __ldg(&g_csw[idx + 2]);
        int2 v3 = __ldg(&g_csw[idx + 3]);
        body(v0); body(v1); body(v2); body(v3);
    }
    for (; idx < e2; idx++) body(__ldg(&g_csw[idx]));

    float r[V];
    const float* rrow = Rf + (size_t)w * DO;
    if constexpr (V == 4) {
        float4 rv = ((const float4*)rrow)[lane];
        r[0] = rv.x; r[1] = rv.y; r[2] = rv.z; r[3] = rv.w;
    } else {
        float2 rv = ((const float2*)rrow)[lane];
        r[0] = rv.x; r[1] = rv.y;
    }

    float h[V];
    #pragma unroll
    for (int c = 0; c < V; c++) {
        int d = lane * V + c;
        float hv = acc[c] + r[c];
        if (DOBN) {
            float sc = gg[d] * rsqrtf(vv[d] + 1e-5f);
            hv = (hv - mm[d]) * sc + bb[d];
            hv = fmaxf(hv, 0.f);
        }
        h[c] = hv;
    }
    if constexpr (HOUT) {
        __half* out = (__half*)outv;
        if constexpr (V == 4) {
            half2 h0 = __floats2half2_rn(h[0], h[1]);
            half2 h1 = __floats2half2_rn(h[2], h[3]);
            uint2 q; q.x = *(unsigned*)&h0; q.y = *(unsigned*)&h1;
            ((uint2*)(out + (size_t)w * DO))[lane] = q;
        } else {
            half2 h0 = __floats2half2_rn(h[0], h[1]);
            ((unsigned*)(out + (size_t)w * DO))[lane] = *(unsigned*)&h0;
        }
    } else {
        float* out = (float*)outv;
        if constexpr (V == 4) {
            ((float4*)(out + (size_t)w * DO))[lane] =
                make_float4(h[0], h[1], h[2], h[3]);
        } else {
            ((float2*)(out + (size_t)w * DO))[lane] = make_float2(h[0], h[1]);
        }
    }
}

// ---------------------------------------------------------------- launch
extern "C" void kernel_launch(void* const* d_in, const int* in_sizes, int n_in,
                              void* d_out, int out_size) {
    const float* x   = (const float*)d_in[0];
    const void*  ei  = d_in[1];
    const float* Wn0 = (const float*)d_in[2];
    const float* cn0 = (const float*)d_in[3];
    const float* Wr0 = (const float*)d_in[4];
    const float* cr0 = (const float*)d_in[5];
    const float* Wn1 = (const float*)d_in[6];
    const float* cn1 = (const float*)d_in[7];
    const float* Wr1 = (const float*)d_in[8];
    const float* cr1 = (const float*)d_in[9];
    const float* Wn2 = (const float*)d_in[10];
    const float* cn2 = (const float*)d_in[11];
    const float* Wr2 = (const float*)d_in[12];
    const float* cr2 = (const float*)d_in[13];
    const float* g0  = (const float*)d_in[14];
    const float* b0  = (const float*)d_in[15];
    const float* m0  = (const float*)d_in[16];
    const float* v0  = (const float*)d_in[17];
    const float* g1  = (const float*)d_in[18];
    const float* b1  = (const float*)d_in[19];
    const float* m1  = (const float*)d_in[20];
    const float* v1  = (const float*)d_in[21];

    int n = in_sizes[0] / 128;
    int e = in_sizes[1] / 2;
    float* out = (float*)d_out;

    __half *xh, *Hh, *Ph, *W0t, *W1t, *W2t;
    float* Rf;
    cudaGetSymbolAddress((void**)&xh, g_xh);
    cudaGetSymbolAddress((void**)&Hh, g_Hh);
    cudaGetSymbolAddress((void**)&Ph, g_Ph);
    cudaGetSymbolAddress((void**)&Rf, g_R);
    cudaGetSymbolAddress((void**)&W0t, g_W0t);
    cudaGetSymbolAddress((void**)&W1t, g_W1t);
    cudaGetSymbolAddress((void**)&W2t, g_W2t);

    static cudaStream_t s2 = nullptr;
    static cudaEvent_t ev0 = nullptr, ev1 = nullptr;
    if (!s2) {
        cudaStreamCreateWithFlags(&s2, cudaStreamNonBlocking);
        cudaEventCreateWithFlags(&ev0, cudaEventDisableTiming);
        cudaEventCreateWithFlags(&ev1, cudaEventDisableTiming);
    }

    int gx = (n + 127) / 128;

    // s2: gemm0 pipeline (depends only on x / weights) + norm
    cudaEventRecord(ev0, 0);
    cudaStreamWaitEvent(s2, ev0, 0);
    k_x2h<<<(n * 16 + 255) / 256, 256, 0, s2>>>(x, n);
    k_prepw<<<(256 * 128 + 255) / 256, 256, 0, s2>>>(Wn0, Wr0, W0t, 128);
    k_prepw<<<(256 * 128 + 255) / 256, 256, 0, s2>>>(Wn1, Wr1, W1t, 128);
    k_prepw<<<(128 * 128 + 255) / 256, 256, 0, s2>>>(Wn2, Wr2, W2t, 64);
    k_hgemm<<<dim3(gx, 2), 256, 0, s2>>>(xh, W0t, cn0, cr0, Ph, Rf, n, 128);
    k_norm<<<(n + 7) / 8, 256, 0, s2>>>(x, n);
    cudaEventRecord(ev1, s2);

    // stream0: CSR build
    k_detect<<<1, 256>>>(ei, e, n);
    k_init<<<(n + 255) / 256, 256>>>(n);
    k_cnt<<<(e + 255) / 256, 256>>>(ei, e);
    k_scan<<<1, 1024>>>(n);
    k_place<<<(e + 255) / 256, 256>>>(ei, e);

    // join, then serial layer chain
    cudaStreamWaitEvent(0, ev1, 0);
    k_edge_csr<<<(n + 7) / 8, 256>>>(n);
    k_agg<128, true, true><<<(n + 7) / 8, 256>>>(Ph, Rf, g0, b0, m0, v0, Hh, n);
    k_hgemm<<<dim3(gx, 2), 256>>>(Hh, W1t, cn1, cr1, Ph, Rf, n, 128);
    k_agg<128, true, true><<<(n + 7) / 8, 256>>>(Ph, Rf, g1, b1, m1, v1, Hh, n);
    k_hgemm<<<dim3(gx, 1), 256>>>(Hh, W2t, cn2, cr2, Ph, Rf, n, 64);
    k_agg<64, false, false><<<(n + 7) / 8, 256>>>(Ph, Rf, g0, b0, m0, v0, out, n);
}